// round 15
// baseline (speedup 1.0000x reference)
#include <cuda_runtime.h>
#include <stdint.h>

#define N_NODES_MAX 100000
#define N_EDGES_MAX 400000
#define DIM 128
#define AS_LD 132
#define WS_LD 136
#define MLP_SMEM_WORDS (128 * AS_LD + 2 * 128 * WS_LD + 256)
#define MLP_SMEM_BYTES (MLP_SMEM_WORDS * 4)

// ---------------- scratch (device globals; no allocation allowed) ----------
__device__ int   g_deg[N_NODES_MAX];
__device__ int   g_off[N_NODES_MAX];   // chunk-local offsets; after scatter: local END
__device__ int   g_srcs[N_EDGES_MAX];
__device__ int   g_bsum[256];
__device__ int   g_base[256];
__device__ float g_h[(size_t)N_NODES_MAX * DIM];
__device__ float g_sum[DIM];
__device__ float g_sumsq[DIM];
__device__ unsigned g_w1t[128 * WS_LD];
__device__ unsigned g_w2t[128 * WS_LD];
__device__ unsigned g_bar_build;
__device__ unsigned g_bar_mlp;

__device__ __forceinline__ void grid_sync(unsigned* cnt, int grid) {
    __syncthreads();
    if (threadIdx.x == 0) {
        __threadfence();
        unsigned old = atomicAdd(cnt, 1u);
        unsigned target = (old / (unsigned)grid + 1u) * (unsigned)grid;
        while (*(volatile unsigned*)cnt < target) __nanosleep(32);
        __threadfence();
    }
    __syncthreads();
}

__device__ __forceinline__ unsigned f2tf32(float f) {
    unsigned u;
    asm("cvt.rna.tf32.f32 %0, %1;" : "=r"(u) : "f"(f));
    return u;
}

__device__ __forceinline__ void mma_tf32(float c[4], unsigned a0, unsigned a1,
                                         unsigned a2, unsigned a3,
                                         unsigned b0, unsigned b1) {
    asm volatile(
        "mma.sync.aligned.m16n8k8.row.col.f32.tf32.tf32.f32 "
        "{%0,%1,%2,%3}, {%4,%5,%6,%7}, {%8,%9}, {%0,%1,%2,%3};"
        : "+f"(c[0]), "+f"(c[1]), "+f"(c[2]), "+f"(c[3])
        : "r"(a0), "r"(a1), "r"(a2), "r"(a3), "r"(b0), "r"(b1));
}

// =================== K1: persistent CSR builder (3 grid syncs) =============
__global__ void __launch_bounds__(1024, 1)
k_build(const int* __restrict__ ei,
        const float* __restrict__ w1, const float* __restrict__ w2,
        int e, int n, int grid, int chunk) {
    const int t = threadIdx.x;
    const int bid = blockIdx.x;
    const int gtid = bid * 1024 + t;
    const int gstride = grid * 1024;

    __shared__ int wsum[32];
    __shared__ int s_base[256];

    // ---- phase 0: zero counters + BN accumulators; tf32-transpose weights ----
    for (int i = gtid; i < n; i += gstride) g_deg[i] = 0;
    if (gtid < DIM) { g_sum[gtid] = 0.f; g_sumsq[gtid] = 0.f; }
    for (int i = gtid; i < 128 * WS_LD; i += gstride) {
        int k = i / WS_LD, c = i % WS_LD;
        unsigned v1 = 0, v2 = 0;
        if (c < 128) { v1 = f2tf32(w1[c * 128 + k]); v2 = f2tf32(w2[c * 128 + k]); }
        g_w1t[i] = v1;
        g_w2t[i] = v2;
    }
    grid_sync(&g_bar_build, grid);

    // ---- phase 1: in-degree histogram ----
    for (int i = gtid; i < e; i += gstride) {
        int d = __ldg(ei + e + i);
        if ((unsigned)d < (unsigned)n) atomicAdd(&g_deg[d], 1);
    }
    grid_sync(&g_bar_build, grid);

    // ---- phase 2: per-CTA chunk-LOCAL exclusive scan (chunk <= 4096) ----
    const int start = bid * chunk;
    int cnt = n - start;
    if (cnt < 0) cnt = 0;
    if (cnt > chunk) cnt = chunk;

    const int base = t * 4;
    int v0 = 0, v1 = 0, v2 = 0, v3 = 0;
    if (base + 0 < cnt) v0 = g_deg[start + base + 0];
    if (base + 1 < cnt) v1 = g_deg[start + base + 1];
    if (base + 2 < cnt) v2 = g_deg[start + base + 2];
    if (base + 3 < cnt) v3 = g_deg[start + base + 3];
    int tsum = v0 + v1 + v2 + v3;
    int lane = t & 31, w = t >> 5;
    int incl = tsum;
#pragma unroll
    for (int o = 1; o < 32; o <<= 1) {
        int x = __shfl_up_sync(~0u, incl, o);
        if (lane >= o) incl += x;
    }
    if (lane == 31) wsum[w] = incl;
    __syncthreads();
    if (t < 32) {
        int s = wsum[t];
        int i2 = s;
#pragma unroll
        for (int o = 1; o < 32; o <<= 1) {
            int x = __shfl_up_sync(~0u, i2, o);
            if (t >= o) i2 += x;
        }
        wsum[t] = i2 - s;
        if (t == 31) g_bsum[bid] = i2;
    }
    __syncthreads();
    int run = incl - tsum + wsum[w];
    if (base + 0 < cnt) { g_off[start + base + 0] = run; run += v0; }
    if (base + 1 < cnt) { g_off[start + base + 1] = run; run += v1; }
    if (base + 2 < cnt) { g_off[start + base + 2] = run; run += v2; }
    if (base + 3 < cnt) { g_off[start + base + 3] = run; }
    grid_sync(&g_bar_build, grid);

    // ---- phase 3 (CTA-local, no grid sync): full prefix of block totals ----
    if (t < 32) {
        int carry = 0;
        for (int b0 = 0; b0 < grid; b0 += 32) {
            int idx = b0 + t;
            int v = (idx < grid) ? g_bsum[idx] : 0;
            int i2 = v;
#pragma unroll
            for (int o = 1; o < 32; o <<= 1) {
                int x = __shfl_up_sync(~0u, i2, o);
                if (t >= o) i2 += x;
            }
            if (idx < grid) s_base[idx] = carry + i2 - v;
            carry += __shfl_sync(~0u, i2, 31);
        }
    }
    __syncthreads();
    if (t == 0) g_base[bid] = s_base[bid];  // published for k_agg (launch boundary)

    // ---- phase 4: scatter via local cursor + chunk base ----
    for (int i = gtid; i < e; i += gstride) {
        int d = ei[e + i];
        int s = ei[i];
        if ((unsigned)d < (unsigned)n && (unsigned)s < (unsigned)n) {
            int p = atomicAdd(&g_off[d], 1) + s_base[d / chunk];
            if ((unsigned)p < (unsigned)N_EDGES_MAX) g_srcs[p] = s;
        }
    }
}

// =================== K2: per-node gather-sum ===============================
__global__ void k_agg(const float* __restrict__ x, int n, int chunk) {
    int warp = (blockIdx.x * blockDim.x + threadIdx.x) >> 5;
    int lane = threadIdx.x & 31;
    if (warp >= n) return;
    float4 acc = ((const float4*)(x + (size_t)warp * DIM))[lane];
    int end = g_off[warp] + g_base[warp / chunk];
    int e = end - g_deg[warp];
    for (; e + 4 <= end; e += 4) {
        int s0 = g_srcs[e], s1 = g_srcs[e + 1], s2 = g_srcs[e + 2], s3 = g_srcs[e + 3];
        float4 v0 = ((const float4*)(x + (size_t)s0 * DIM))[lane];
        float4 v1 = ((const float4*)(x + (size_t)s1 * DIM))[lane];
        float4 v2 = ((const float4*)(x + (size_t)s2 * DIM))[lane];
        float4 v3 = ((const float4*)(x + (size_t)s3 * DIM))[lane];
        acc.x += v0.x + v1.x + v2.x + v3.x;
        acc.y += v0.y + v1.y + v2.y + v3.y;
        acc.z += v0.z + v1.z + v2.z + v3.z;
        acc.w += v0.w + v1.w + v2.w + v3.w;
    }
    for (; e < end; e++) {
        float4 v = ((const float4*)(x + (size_t)g_srcs[e] * DIM))[lane];
        acc.x += v.x; acc.y += v.y; acc.z += v.z; acc.w += v.w;
    }
    ((float4*)(g_h + (size_t)warp * DIM))[lane] = acc;
}

// ========= K3: persistent MLP + BN, 256 threads, 8 warps @ 64x32 tiles =====
__global__ void __launch_bounds__(256, 1)
k_mlp(const float* __restrict__ b1, const float* __restrict__ b2,
      const float* __restrict__ gamma, const float* __restrict__ beta,
      float* __restrict__ out, int M, int ntiles, int grid) {
    extern __shared__ unsigned sm[];
    unsigned* As = sm;                       // 128 x AS_LD
    unsigned* W1s = sm + 128 * AS_LD;        // 128 x WS_LD  [k][n]
    unsigned* W2s = W1s + 128 * WS_LD;       // 128 x WS_LD
    float* Bs = (float*)(W2s + 128 * WS_LD); // 256 floats: b1 | b2
    float* Asf = (float*)As;

    const int t = threadIdx.x;
    const int lane = t & 31, wid = t >> 5;
    const int g = lane >> 2, tig = lane & 3;
    const int mi = wid & 1;   // 2 row-blocks of 64
    const int nq = wid >> 1;  // 4 col-blocks of 32

    // one-time: both (pre-transposed) weight matrices resident; biases staged
    for (int i = t; i < 128 * WS_LD; i += 256) {
        W1s[i] = g_w1t[i];
        W2s[i] = g_w2t[i];
    }
    if (t < 128) { Bs[t] = b1[t]; Bs[128 + t] = b2[t]; }

    // BN per-thread accumulators: 8 column slots (nt*2 + parity)
    float bns[8], bnss[8];
#pragma unroll
    for (int q = 0; q < 8; q++) { bns[q] = 0.f; bnss[q] = 0.f; }

    for (int tile = blockIdx.x; tile < ntiles; tile += grid) {
        const int row0 = tile * 128;

        // stage A tile from g_h (tf32-rounded)
        for (int i = t; i < 128 * 32; i += 256) {
            int r = i >> 5, c4 = i & 31;
            float4 v = make_float4(0.f, 0.f, 0.f, 0.f);
            if (row0 + r < M) v = *(const float4*)(g_h + (size_t)(row0 + r) * DIM + c4 * 4);
            uint4 u = make_uint4(f2tf32(v.x), f2tf32(v.y), f2tf32(v.z), f2tf32(v.w));
            *(uint4*)(As + r * AS_LD + c4 * 4) = u;
        }
        __syncthreads();

        float c[4][4][4];

        // ---------- layer 1 ----------
#pragma unroll
        for (int m = 0; m < 4; m++)
#pragma unroll
            for (int nt = 0; nt < 4; nt++)
#pragma unroll
                for (int j = 0; j < 4; j++) c[m][nt][j] = 0.f;

#pragma unroll 4
        for (int ks = 0; ks < 16; ks++) {
            int k0 = ks * 8;
            unsigned a[4][4];
#pragma unroll
            for (int m = 0; m < 4; m++) {
                int rb = mi * 64 + m * 16;
                a[m][0] = As[(rb + g) * AS_LD + k0 + tig];
                a[m][1] = As[(rb + g + 8) * AS_LD + k0 + tig];
                a[m][2] = As[(rb + g) * AS_LD + k0 + tig + 4];
                a[m][3] = As[(rb + g + 8) * AS_LD + k0 + tig + 4];
            }
#pragma unroll
            for (int nt = 0; nt < 4; nt++) {
                unsigned bb0 = W1s[(k0 + tig) * WS_LD + nq * 32 + nt * 8 + g];
                unsigned bb1 = W1s[(k0 + tig + 4) * WS_LD + nq * 32 + nt * 8 + g];
#pragma unroll
                for (int m = 0; m < 4; m++)
                    mma_tf32(c[m][nt], a[m][0], a[m][1], a[m][2], a[m][3], bb0, bb1);
            }
        }
        __syncthreads();

        // epilogue 1: relu(c + b1) -> As (tf32)
#pragma unroll
        for (int m = 0; m < 4; m++)
#pragma unroll
            for (int nt = 0; nt < 4; nt++) {
                int cc = nq * 32 + nt * 8 + tig * 2;
                float bb0 = Bs[cc], bb1v = Bs[cc + 1];
                int r0l = mi * 64 + m * 16 + g;
                float v00 = fmaxf(c[m][nt][0] + bb0, 0.f);
                float v01 = fmaxf(c[m][nt][1] + bb1v, 0.f);
                float v10 = fmaxf(c[m][nt][2] + bb0, 0.f);
                float v11 = fmaxf(c[m][nt][3] + bb1v, 0.f);
                *(uint2*)(As + r0l * AS_LD + cc) = make_uint2(f2tf32(v00), f2tf32(v01));
                *(uint2*)(As + (r0l + 8) * AS_LD + cc) = make_uint2(f2tf32(v10), f2tf32(v11));
            }
        __syncthreads();

        // ---------- layer 2 ----------
#pragma unroll
        for (int m = 0; m < 4; m++)
#pragma unroll
            for (int nt = 0; nt < 4; nt++)
#pragma unroll
                for (int j = 0; j < 4; j++) c[m][nt][j] = 0.f;

#pragma unroll 4
        for (int ks = 0; ks < 16; ks++) {
            int k0 = ks * 8;
            unsigned a[4][4];
#pragma unroll
            for (int m = 0; m < 4; m++) {
                int rb = mi * 64 + m * 16;
                a[m][0] = As[(rb + g) * AS_LD + k0 + tig];
                a[m][1] = As[(rb + g + 8) * AS_LD + k0 + tig];
                a[m][2] = As[(rb + g) * AS_LD + k0 + tig + 4];
                a[m][3] = As[(rb + g + 8) * AS_LD + k0 + tig + 4];
            }
#pragma unroll
            for (int nt = 0; nt < 4; nt++) {
                unsigned bb0 = W2s[(k0 + tig) * WS_LD + nq * 32 + nt * 8 + g];
                unsigned bb1 = W2s[(k0 + tig + 4) * WS_LD + nq * 32 + nt * 8 + g];
#pragma unroll
                for (int m = 0; m < 4; m++)
                    mma_tf32(c[m][nt], a[m][0], a[m][1], a[m][2], a[m][3], bb0, bb1);
            }
        }

        // epilogue 2: relu(c + b2) -> gmem directly + BN accumulation from regs
#pragma unroll
        for (int m = 0; m < 4; m++)
#pragma unroll
            for (int nt = 0; nt < 4; nt++) {
                int cc = nq * 32 + nt * 8 + tig * 2;
                float bb0 = Bs[128 + cc], bb1v = Bs[128 + cc + 1];
                int rA = row0 + mi * 64 + m * 16 + g;
                int rB = rA + 8;
                float v00 = fmaxf(c[m][nt][0] + bb0, 0.f);
                float v01 = fmaxf(c[m][nt][1] + bb1v, 0.f);
                float v10 = fmaxf(c[m][nt][2] + bb0, 0.f);
                float v11 = fmaxf(c[m][nt][3] + bb1v, 0.f);
                if (rA < M) {
                    *(float2*)(out + (size_t)rA * DIM + cc) = make_float2(v00, v01);
                    bns[nt * 2 + 0] += v00; bnss[nt * 2 + 0] += v00 * v00;
                    bns[nt * 2 + 1] += v01; bnss[nt * 2 + 1] += v01 * v01;
                }
                if (rB < M) {
                    *(float2*)(out + (size_t)rB * DIM + cc) = make_float2(v10, v11);
                    bns[nt * 2 + 0] += v10; bnss[nt * 2 + 0] += v10 * v10;
                    bns[nt * 2 + 1] += v11; bnss[nt * 2 + 1] += v11 * v11;
                }
            }
        __syncthreads();  // all layer-2 As reads done before next A staging
    }

    // BN: reduce the 8 g-lanes sharing each (nq, tig) column, then atomics
#pragma unroll
    for (int q = 0; q < 8; q++) {
        float s = bns[q], ss = bnss[q];
        s += __shfl_down_sync(~0u, s, 16); ss += __shfl_down_sync(~0u, ss, 16);
        s += __shfl_down_sync(~0u, s, 8);  ss += __shfl_down_sync(~0u, ss, 8);
        s += __shfl_down_sync(~0u, s, 4);  ss += __shfl_down_sync(~0u, ss, 4);
        if (lane < 4) {
            int col = nq * 32 + (q >> 1) * 8 + lane * 2 + (q & 1);
            atomicAdd(&g_sum[col], s);
            atomicAdd(&g_sumsq[col], ss);
        }
    }

    grid_sync(&g_bar_mlp, grid);

    // each CTA computes scale/shift locally into SMEM (reuse As region)
    if (t < DIM) {
        float inv = 1.f / (float)M;
        float mean = g_sum[t] * inv;
        float var = fmaxf(g_sumsq[t] * inv - mean * mean, 0.f);
        float sc = gamma[t] * rsqrtf(var + 1e-5f);
        Asf[t] = sc;
        Asf[128 + t] = beta[t] - mean * sc;
    }
    __syncthreads();

    // apply BN in-place over out (float4)
    int total4 = M * (DIM / 4);
    for (int i = blockIdx.x * 256 + t; i < total4; i += grid * 256) {
        int c4 = (i & 31) * 4;
        float4 v = ((float4*)out)[i];
        float4 sc = *(const float4*)(Asf + c4);
        float4 sh = *(const float4*)(Asf + 128 + c4);
        v.x = v.x * sc.x + sh.x;
        v.y = v.y * sc.y + sh.y;
        v.z = v.z * sc.z + sh.z;
        v.w = v.w * sc.w + sh.w;
        ((float4*)out)[i] = v;
    }
}

extern "C" void kernel_launch(void* const* d_in, const int* in_sizes, int n_in,
                              void* d_out, int out_size) {
    const float* feat = (const float*)d_in[0];
    const int* ei = (const int*)d_in[1];  // int32 (JAX x64 disabled)
    const float* w1 = (const float*)d_in[2];
    const float* b1 = (const float*)d_in[3];
    const float* w2 = (const float*)d_in[4];
    const float* b2 = (const float*)d_in[5];
    const float* gamma = (const float*)d_in[6];
    const float* beta = (const float*)d_in[7];
    float* out = (float*)d_out;

    int n = in_sizes[0] / DIM;   // 100000
    int e = in_sizes[1] / 2;     // 400000
    int ntiles = (n + 127) / 128;

    int sms = 0;
    cudaDeviceGetAttribute(&sms, cudaDevAttrMultiProcessorCount, 0);
    if (sms <= 0) sms = 148;
    if (sms > 256) sms = 256;
    int gm = sms < ntiles ? sms : ntiles;
    int chunk = (n + sms - 1) / sms;

    cudaFuncSetAttribute(k_mlp, cudaFuncAttributeMaxDynamicSharedMemorySize, MLP_SMEM_BYTES);

    k_build<<<sms, 1024>>>(ei, w1, w2, e, n, sms, chunk);
    k_agg<<<(n + 7) / 8, 256>>>(feat, n, chunk);
    k_mlp<<<gm, 256, MLP_SMEM_BYTES>>>(b1, b2, gamma, beta, out, n, ntiles, gm);
}

// round 17
// speedup vs baseline: 1.1386x; 1.1386x over previous
#include <cuda_runtime.h>
#include <stdint.h>

#define N_NODES_MAX 100000
#define N_EDGES_MAX 400000
#define DIM 128
#define AS_LD 132
#define WS_LD 136
#define MLP_SMEM_WORDS (128 * AS_LD + 2 * 128 * WS_LD + 256)
#define MLP_SMEM_BYTES (MLP_SMEM_WORDS * 4)

// ---------------- scratch (device globals; no allocation allowed) ----------
__device__ int   g_deg[N_NODES_MAX];
__device__ int   g_off[N_NODES_MAX];   // chunk-local offsets; after scatter: local END
__device__ int   g_srcs[N_EDGES_MAX];
__device__ int   g_bsum[256];
__device__ float g_h[(size_t)N_NODES_MAX * DIM];
__device__ float g_sum[DIM];
__device__ float g_sumsq[DIM];
__device__ unsigned g_w1t[128 * WS_LD];
__device__ unsigned g_w2t[128 * WS_LD];
__device__ unsigned g_bar_build;
__device__ unsigned g_bar_mlp;

__device__ __forceinline__ void grid_sync(unsigned* cnt, int grid) {
    __syncthreads();
    if (threadIdx.x == 0) {
        __threadfence();
        unsigned old = atomicAdd(cnt, 1u);
        unsigned target = (old / (unsigned)grid + 1u) * (unsigned)grid;
        while (*(volatile unsigned*)cnt < target) __nanosleep(32);
        __threadfence();
    }
    __syncthreads();
}

__device__ __forceinline__ unsigned f2tf32(float f) {
    unsigned u;
    asm("cvt.rna.tf32.f32 %0, %1;" : "=r"(u) : "f"(f));
    return u;
}

__device__ __forceinline__ void mma_tf32(float c[4], unsigned a0, unsigned a1,
                                         unsigned a2, unsigned a3,
                                         unsigned b0, unsigned b1) {
    asm volatile(
        "mma.sync.aligned.m16n8k8.row.col.f32.tf32.tf32.f32 "
        "{%0,%1,%2,%3}, {%4,%5,%6,%7}, {%8,%9}, {%0,%1,%2,%3};"
        : "+f"(c[0]), "+f"(c[1]), "+f"(c[2]), "+f"(c[3])
        : "r"(a0), "r"(a1), "r"(a2), "r"(a3), "r"(b0), "r"(b1));
}

// ====== K1: persistent CSR build + gather-aggregate (4 grid syncs) =========
// phases: zero+weights | hist | chunk scan (+local prefix) | scatter | gather
// chunk is a power of two (1 << cshift), so no integer division anywhere.
__global__ void __launch_bounds__(1024, 1)
k_buildagg(const int* __restrict__ ei,
           const float* __restrict__ w1, const float* __restrict__ w2,
           const float* __restrict__ x,
           int e, int n, int grid, int cshift) {
    const int t = threadIdx.x;
    const int bid = blockIdx.x;
    const int gtid = bid * 1024 + t;
    const int gstride = grid * 1024;
    const int chunk = 1 << cshift;
    const int nchunks = (n + chunk - 1) >> cshift;

    __shared__ int wsum[32];
    __shared__ int s_base[256];

    // ---- phase 0: zero counters + BN accumulators; tf32-transpose weights ----
    for (int i = gtid; i < n; i += gstride) g_deg[i] = 0;
    if (gtid < DIM) { g_sum[gtid] = 0.f; g_sumsq[gtid] = 0.f; }
    for (int i = gtid; i < 128 * WS_LD; i += gstride) {
        int k = i / WS_LD, c = i % WS_LD;
        unsigned v1 = 0, v2 = 0;
        if (c < 128) { v1 = f2tf32(w1[c * 128 + k]); v2 = f2tf32(w2[c * 128 + k]); }
        g_w1t[i] = v1;
        g_w2t[i] = v2;
    }
    grid_sync(&g_bar_build, grid);

    // ---- phase 1: in-degree histogram ----
    for (int i = gtid; i < e; i += gstride) {
        int d = __ldg(ei + e + i);
        if ((unsigned)d < (unsigned)n) atomicAdd(&g_deg[d], 1);
    }
    grid_sync(&g_bar_build, grid);

    // ---- phase 2: per-CTA chunk-LOCAL exclusive scan (chunk <= 1024 here) ----
    const int start = bid << cshift;
    int cnt = n - start;
    if (cnt < 0) cnt = 0;
    if (cnt > chunk) cnt = chunk;

    int lane = t & 31, w = t >> 5;
    {
        int v = (t < cnt) ? g_deg[start + t] : 0;
        int incl = v;
#pragma unroll
        for (int o = 1; o < 32; o <<= 1) {
            int xx = __shfl_up_sync(~0u, incl, o);
            if (lane >= o) incl += xx;
        }
        if (lane == 31) wsum[w] = incl;
        __syncthreads();
        if (t < 32) {
            int s = wsum[t];
            int i2 = s;
#pragma unroll
            for (int o = 1; o < 32; o <<= 1) {
                int xx = __shfl_up_sync(~0u, i2, o);
                if (t >= o) i2 += xx;
            }
            wsum[t] = i2 - s;
            if (t == 31 && bid < 256) g_bsum[bid] = i2;
        }
        __syncthreads();
        if (t < cnt) g_off[start + t] = incl - v + wsum[w];
    }
    grid_sync(&g_bar_build, grid);

    // ---- phase 3 (CTA-local, no grid sync): full prefix of chunk totals ----
    if (t < 32) {
        int carry = 0;
        for (int b0 = 0; b0 < nchunks; b0 += 32) {
            int idx = b0 + t;
            int v = (idx < nchunks) ? g_bsum[idx] : 0;
            int i2 = v;
#pragma unroll
            for (int o = 1; o < 32; o <<= 1) {
                int xx = __shfl_up_sync(~0u, i2, o);
                if (t >= o) i2 += xx;
            }
            if (idx < nchunks) s_base[idx] = carry + i2 - v;
            carry += __shfl_sync(~0u, i2, 31);
        }
    }
    __syncthreads();

    // ---- phase 4: scatter via local cursor + chunk base (shift, no div) ----
    for (int i = gtid; i < e; i += gstride) {
        int d = ei[e + i];
        int s = ei[i];
        if ((unsigned)d < (unsigned)n && (unsigned)s < (unsigned)n) {
            int p = atomicAdd(&g_off[d], 1) + s_base[d >> cshift];
            if ((unsigned)p < (unsigned)N_EDGES_MAX) g_srcs[p] = s;
        }
    }
    grid_sync(&g_bar_build, grid);

    // ---- phase 5: per-node gather-sum (1 warp/node, grid-strided; NO
    //      syncs after this point -> warps stay fully independent) ----
    const int nwarps = grid * 32;
    for (int node = bid * 32 + w; node < n; node += nwarps) {
        float4 acc = ((const float4*)(x + (size_t)node * DIM))[lane];
        int end = g_off[node] + s_base[node >> cshift];
        int eidx = end - g_deg[node];
        for (; eidx + 4 <= end; eidx += 4) {
            int s0 = g_srcs[eidx], s1 = g_srcs[eidx + 1];
            int s2 = g_srcs[eidx + 2], s3 = g_srcs[eidx + 3];
            float4 v0 = ((const float4*)(x + (size_t)s0 * DIM))[lane];
            float4 v1 = ((const float4*)(x + (size_t)s1 * DIM))[lane];
            float4 v2 = ((const float4*)(x + (size_t)s2 * DIM))[lane];
            float4 v3 = ((const float4*)(x + (size_t)s3 * DIM))[lane];
            acc.x += v0.x + v1.x + v2.x + v3.x;
            acc.y += v0.y + v1.y + v2.y + v3.y;
            acc.z += v0.z + v1.z + v2.z + v3.z;
            acc.w += v0.w + v1.w + v2.w + v3.w;
        }
        for (; eidx < end; eidx++) {
            float4 v = ((const float4*)(x + (size_t)g_srcs[eidx] * DIM))[lane];
            acc.x += v.x; acc.y += v.y; acc.z += v.z; acc.w += v.w;
        }
        ((float4*)(g_h + (size_t)node * DIM))[lane] = acc;
    }
}

// =================== K2: persistent MLP + BN (512 thr, direct STG) =========
__global__ void __launch_bounds__(512, 1)
k_mlp(const float* __restrict__ b1, const float* __restrict__ b2,
      const float* __restrict__ gamma, const float* __restrict__ beta,
      float* __restrict__ out, int M, int ntiles, int grid) {
    extern __shared__ unsigned sm[];
    unsigned* As = sm;                       // 128 x AS_LD
    unsigned* W1s = sm + 128 * AS_LD;        // 128 x WS_LD  [k][n]
    unsigned* W2s = W1s + 128 * WS_LD;       // 128 x WS_LD
    float* Bs = (float*)(W2s + 128 * WS_LD); // 256 floats: b1 | b2
    float* Asf = (float*)As;

    const int t = threadIdx.x;
    const int lane = t & 31, wid = t >> 5;
    const int g = lane >> 2, tig = lane & 3;
    const int mi = wid & 3;   // 4 row-blocks of 32
    const int nq = wid >> 2;  // 4 col-blocks of 32

    // one-time: both (pre-transposed) weight matrices resident; biases staged
    for (int i = t; i < 128 * WS_LD; i += 512) {
        W1s[i] = g_w1t[i];
        W2s[i] = g_w2t[i];
    }
    if (t < 128) { Bs[t] = b1[t]; Bs[128 + t] = b2[t]; }

    // BN per-thread accumulators: 8 column slots (nt*2 + parity)
    float bns[8], bnss[8];
#pragma unroll
    for (int q = 0; q < 8; q++) { bns[q] = 0.f; bnss[q] = 0.f; }

    for (int tile = blockIdx.x; tile < ntiles; tile += grid) {
        const int row0 = tile * 128;

        // stage A tile from g_h (tf32-rounded)
        for (int i = t; i < 128 * 32; i += 512) {
            int r = i >> 5, c4 = i & 31;
            float4 v = make_float4(0.f, 0.f, 0.f, 0.f);
            if (row0 + r < M) v = *(const float4*)(g_h + (size_t)(row0 + r) * DIM + c4 * 4);
            uint4 u = make_uint4(f2tf32(v.x), f2tf32(v.y), f2tf32(v.z), f2tf32(v.w));
            *(uint4*)(As + r * AS_LD + c4 * 4) = u;
        }
        __syncthreads();

        float c[2][4][4];

        // ---------- layer 1 ----------
#pragma unroll
        for (int m = 0; m < 2; m++)
#pragma unroll
            for (int nt = 0; nt < 4; nt++)
#pragma unroll
                for (int j = 0; j < 4; j++) c[m][nt][j] = 0.f;

#pragma unroll 4
        for (int ks = 0; ks < 16; ks++) {
            int k0 = ks * 8;
            unsigned a[2][4];
#pragma unroll
            for (int m = 0; m < 2; m++) {
                int rb = mi * 32 + m * 16;
                a[m][0] = As[(rb + g) * AS_LD + k0 + tig];
                a[m][1] = As[(rb + g + 8) * AS_LD + k0 + tig];
                a[m][2] = As[(rb + g) * AS_LD + k0 + tig + 4];
                a[m][3] = As[(rb + g + 8) * AS_LD + k0 + tig + 4];
            }
#pragma unroll
            for (int nt = 0; nt < 4; nt++) {
                unsigned bb0 = W1s[(k0 + tig) * WS_LD + nq * 32 + nt * 8 + g];
                unsigned bb1 = W1s[(k0 + tig + 4) * WS_LD + nq * 32 + nt * 8 + g];
                mma_tf32(c[0][nt], a[0][0], a[0][1], a[0][2], a[0][3], bb0, bb1);
                mma_tf32(c[1][nt], a[1][0], a[1][1], a[1][2], a[1][3], bb0, bb1);
            }
        }
        __syncthreads();

        // epilogue 1: relu(c + b1) -> As (tf32)
#pragma unroll
        for (int m = 0; m < 2; m++)
#pragma unroll
            for (int nt = 0; nt < 4; nt++) {
                int cc = nq * 32 + nt * 8 + tig * 2;
                float bb0 = Bs[cc], bb1v = Bs[cc + 1];
                int r0l = mi * 32 + m * 16 + g;
                float v00 = fmaxf(c[m][nt][0] + bb0, 0.f);
                float v01 = fmaxf(c[m][nt][1] + bb1v, 0.f);
                float v10 = fmaxf(c[m][nt][2] + bb0, 0.f);
                float v11 = fmaxf(c[m][nt][3] + bb1v, 0.f);
                *(uint2*)(As + r0l * AS_LD + cc) = make_uint2(f2tf32(v00), f2tf32(v01));
                *(uint2*)(As + (r0l + 8) * AS_LD + cc) = make_uint2(f2tf32(v10), f2tf32(v11));
            }
        __syncthreads();

        // ---------- layer 2 ----------
#pragma unroll
        for (int m = 0; m < 2; m++)
#pragma unroll
            for (int nt = 0; nt < 4; nt++)
#pragma unroll
                for (int j = 0; j < 4; j++) c[m][nt][j] = 0.f;

#pragma unroll 4
        for (int ks = 0; ks < 16; ks++) {
            int k0 = ks * 8;
            unsigned a[2][4];
#pragma unroll
            for (int m = 0; m < 2; m++) {
                int rb = mi * 32 + m * 16;
                a[m][0] = As[(rb + g) * AS_LD + k0 + tig];
                a[m][1] = As[(rb + g + 8) * AS_LD + k0 + tig];
                a[m][2] = As[(rb + g) * AS_LD + k0 + tig + 4];
                a[m][3] = As[(rb + g + 8) * AS_LD + k0 + tig + 4];
            }
#pragma unroll
            for (int nt = 0; nt < 4; nt++) {
                unsigned bb0 = W2s[(k0 + tig) * WS_LD + nq * 32 + nt * 8 + g];
                unsigned bb1 = W2s[(k0 + tig + 4) * WS_LD + nq * 32 + nt * 8 + g];
                mma_tf32(c[0][nt], a[0][0], a[0][1], a[0][2], a[0][3], bb0, bb1);
                mma_tf32(c[1][nt], a[1][0], a[1][1], a[1][2], a[1][3], bb0, bb1);
            }
        }

        // epilogue 2: relu(c + b2) -> gmem directly + BN accumulation from regs
#pragma unroll
        for (int m = 0; m < 2; m++)
#pragma unroll
            for (int nt = 0; nt < 4; nt++) {
                int cc = nq * 32 + nt * 8 + tig * 2;
                float bb0 = Bs[128 + cc], bb1v = Bs[128 + cc + 1];
                int rA = row0 + mi * 32 + m * 16 + g;
                int rB = rA + 8;
                float v00 = fmaxf(c[m][nt][0] + bb0, 0.f);
                float v01 = fmaxf(c[m][nt][1] + bb1v, 0.f);
                float v10 = fmaxf(c[m][nt][2] + bb0, 0.f);
                float v11 = fmaxf(c[m][nt][3] + bb1v, 0.f);
                if (rA < M) {
                    *(float2*)(out + (size_t)rA * DIM + cc) = make_float2(v00, v01);
                    bns[nt * 2 + 0] += v00; bnss[nt * 2 + 0] += v00 * v00;
                    bns[nt * 2 + 1] += v01; bnss[nt * 2 + 1] += v01 * v01;
                }
                if (rB < M) {
                    *(float2*)(out + (size_t)rB * DIM + cc) = make_float2(v10, v11);
                    bns[nt * 2 + 0] += v10; bnss[nt * 2 + 0] += v10 * v10;
                    bns[nt * 2 + 1] += v11; bnss[nt * 2 + 1] += v11 * v11;
                }
            }
        __syncthreads();  // all layer-2 As reads done before next A staging
    }

    // BN: reduce the 8 g-lanes sharing each (nq, tig) column, then atomics
#pragma unroll
    for (int q = 0; q < 8; q++) {
        float s = bns[q], ss = bnss[q];
        s += __shfl_down_sync(~0u, s, 16); ss += __shfl_down_sync(~0u, ss, 16);
        s += __shfl_down_sync(~0u, s, 8);  ss += __shfl_down_sync(~0u, ss, 8);
        s += __shfl_down_sync(~0u, s, 4);  ss += __shfl_down_sync(~0u, ss, 4);
        if (lane < 4) {
            int col = nq * 32 + (q >> 1) * 8 + lane * 2 + (q & 1);
            atomicAdd(&g_sum[col], s);
            atomicAdd(&g_sumsq[col], ss);
        }
    }

    grid_sync(&g_bar_mlp, grid);

    // each CTA computes scale/shift locally into SMEM (reuse As region)
    if (t < DIM) {
        float inv = 1.f / (float)M;
        float mean = g_sum[t] * inv;
        float var = fmaxf(g_sumsq[t] * inv - mean * mean, 0.f);
        float sc = gamma[t] * rsqrtf(var + 1e-5f);
        Asf[t] = sc;
        Asf[128 + t] = beta[t] - mean * sc;
    }
    __syncthreads();

    // apply BN in-place over out (float4)
    int total4 = M * (DIM / 4);
    for (int i = blockIdx.x * 512 + t; i < total4; i += grid * 512) {
        int c4 = (i & 31) * 4;
        float4 v = ((float4*)out)[i];
        float4 sc = *(const float4*)(Asf + c4);
        float4 sh = *(const float4*)(Asf + 128 + c4);
        v.x = v.x * sc.x + sh.x;
        v.y = v.y * sc.y + sh.y;
        v.z = v.z * sc.z + sh.z;
        v.w = v.w * sc.w + sh.w;
        ((float4*)out)[i] = v;
    }
}

extern "C" void kernel_launch(void* const* d_in, const int* in_sizes, int n_in,
                              void* d_out, int out_size) {
    const float* feat = (const float*)d_in[0];
    const int* ei = (const int*)d_in[1];  // int32 (JAX x64 disabled)
    const float* w1 = (const float*)d_in[2];
    const float* b1 = (const float*)d_in[3];
    const float* w2 = (const float*)d_in[4];
    const float* b2 = (const float*)d_in[5];
    const float* gamma = (const float*)d_in[6];
    const float* beta = (const float*)d_in[7];
    float* out = (float*)d_out;

    int n = in_sizes[0] / DIM;   // 100000
    int e = in_sizes[1] / 2;     // 400000
    int ntiles = (n + 127) / 128;

    int sms = 0;
    cudaDeviceGetAttribute(&sms, cudaDevAttrMultiProcessorCount, 0);
    if (sms <= 0) sms = 148;
    if (sms > 256) sms = 256;
    int gm = sms < ntiles ? sms : ntiles;

    // power-of-two chunk: smallest shift with (sms << shift) >= n, chunk <= 1024
    int cshift = 0;
    while ((sms << cshift) < n && cshift < 10) cshift++;
    // (sms=152, n=100000 -> cshift=10, nchunks=98 <= sms; scan phase fits)

    cudaFuncSetAttribute(k_mlp, cudaFuncAttributeMaxDynamicSharedMemorySize, MLP_SMEM_BYTES);

    k_buildagg<<<sms, 1024>>>(ei, w1, w2, feat, e, n, sms, cshift);
    k_mlp<<<gm, 512, MLP_SMEM_BYTES>>>(b1, b2, gamma, beta, out, n, ntiles, gm);
}